// round 3
// baseline (speedup 1.0000x reference)
#include <cuda_runtime.h>
#include <cuda_bf16.h>
#include <math_constants.h>

// Problem constants
#define BB 16
#define CC 3
#define MM 512
#define NN 512
#define MNP (MM * NN)                 // 262144 pixels per (b, c) plane
#define PIX (BB * MNP)                // 4,194,304 pixels
#define PIX_PER_THREAD 4
#define THREADS1 256
#define BLOCKS1 (PIX / PIX_PER_THREAD / THREADS1)   // 4096
#define EPS_F 1e-6f
#define T1_CLIP_F 1e7f

// Fixed scratch for block partials (no allocation allowed)
__device__ float g_psum[BLOCKS1];
__device__ float g_pmax[BLOCKS1];

__global__ __launch_bounds__(THREADS1) void maploss_main(
    const float* __restrict__ target,
    const float* __restrict__ mu,
    const float* __restrict__ sigma_y)
{
    const int t = blockIdx.x * THREADS1 + threadIdx.x;   // 0 .. PIX/4-1
    const int p0 = t * PIX_PER_THREAD;                   // first pixel
    const int b  = p0 >> 18;                             // / MNP
    const int r  = p0 & (MNP - 1);                       // offset within image

    // --- sigma_y: 9 contiguous floats/pixel, 4 pixels = 36 floats = 9 float4 ---
    float4 sv[9];
    const float4* sp = reinterpret_cast<const float4*>(sigma_y + (size_t)p0 * 9);
#pragma unroll
    for (int i = 0; i < 9; i++) sv[i] = sp[i];
    const float* sf = reinterpret_cast<const float*>(sv);

    // --- target - mu, per channel, 4 consecutive pixels each ---
    const size_t base = (size_t)b * (CC * MNP) + r;
    float4 t0 = *reinterpret_cast<const float4*>(target + base);
    float4 t1 = *reinterpret_cast<const float4*>(target + base + MNP);
    float4 t2 = *reinterpret_cast<const float4*>(target + base + 2 * MNP);
    float4 u0 = *reinterpret_cast<const float4*>(mu + base);
    float4 u1 = *reinterpret_cast<const float4*>(mu + base + MNP);
    float4 u2 = *reinterpret_cast<const float4*>(mu + base + 2 * MNP);

    float d0[4] = { t0.x - u0.x, t0.y - u0.y, t0.z - u0.z, t0.w - u0.w };
    float d1[4] = { t1.x - u1.x, t1.y - u1.y, t1.z - u1.z, t1.w - u1.w };
    float d2[4] = { t2.x - u2.x, t2.y - u2.y, t2.z - u2.z, t2.w - u2.w };

    float sumv = 0.0f;
    float maxv = -CUDART_INF_F;

#pragma unroll
    for (int j = 0; j < 4; j++) {
        const float* s = sf + 9 * j;   // row-major 3x3, symmetric
        const float a  = s[0], bq = s[1], c = s[2];
        const float d  = s[4], e  = s[5];
        const float f  = s[8];

        // cofactors (adjugate of symmetric 3x3)
        const float A00 = d * f - e * e;
        const float A01 = c * e - bq * f;
        const float A02 = bq * e - c * d;
        const float A11 = a * f - c * c;
        const float A12 = bq * c - a * e;
        const float A22 = a * d - bq * bq;

        const float det = a * A00 + bq * A01 + c * A02;

        const float x = d0[j], y = d1[j], z = d2[j];
        const float q =  x * x * A00 + y * y * A11 + z * z * A22
                      + 2.0f * (x * y * A01 + x * z * A02 + y * z * A12);

        const float t1v = 0.5f * q * __frcp_rn(det);
        const float dv  = 0.5f * __logf(fmaxf(det, EPS_F));

        sumv += t1v + dv;
        maxv  = fmaxf(maxv, t1v);
    }

    // --- warp reduce ---
#pragma unroll
    for (int off = 16; off > 0; off >>= 1) {
        sumv += __shfl_down_sync(0xFFFFFFFFu, sumv, off);
        maxv  = fmaxf(maxv, __shfl_down_sync(0xFFFFFFFFu, maxv, off));
    }

    __shared__ float ssum[THREADS1 / 32];
    __shared__ float smax[THREADS1 / 32];
    const int lane = threadIdx.x & 31;
    const int wid  = threadIdx.x >> 5;
    if (lane == 0) { ssum[wid] = sumv; smax[wid] = maxv; }
    __syncthreads();

    if (wid == 0) {
        float s2 = (lane < THREADS1 / 32) ? ssum[lane] : 0.0f;
        float m2 = (lane < THREADS1 / 32) ? smax[lane] : -CUDART_INF_F;
#pragma unroll
        for (int off = 4; off > 0; off >>= 1) {
            s2 += __shfl_down_sync(0xFFFFFFFFu, s2, off);
            m2  = fmaxf(m2, __shfl_down_sync(0xFFFFFFFFu, m2, off));
        }
        if (lane == 0) {
            g_psum[blockIdx.x] = s2;
            g_pmax[blockIdx.x] = m2;
        }
    }
}

__global__ __launch_bounds__(1024) void maploss_finish(float* __restrict__ out)
{
    float s = 0.0f;
    float m = -CUDART_INF_F;
#pragma unroll
    for (int i = 0; i < BLOCKS1 / 1024; i++) {
        const int idx = threadIdx.x + i * 1024;
        s += g_psum[idx];
        m  = fmaxf(m, g_pmax[idx]);
    }
#pragma unroll
    for (int off = 16; off > 0; off >>= 1) {
        s += __shfl_down_sync(0xFFFFFFFFu, s, off);
        m  = fmaxf(m, __shfl_down_sync(0xFFFFFFFFu, m, off));
    }
    __shared__ float ssum[32];
    __shared__ float smax[32];
    const int lane = threadIdx.x & 31;
    const int wid  = threadIdx.x >> 5;
    if (lane == 0) { ssum[wid] = s; smax[wid] = m; }
    __syncthreads();
    if (wid == 0) {
        float s2 = (lane < 32) ? ssum[lane] : 0.0f;
        float m2 = (lane < 32) ? smax[lane] : -CUDART_INF_F;
#pragma unroll
        for (int off = 16; off > 0; off >>= 1) {
            s2 += __shfl_down_sync(0xFFFFFFFFu, s2, off);
            m2  = fmaxf(m2, __shfl_down_sync(0xFFFFFFFFu, m2, off));
        }
        if (lane == 0) {
            const float mean = s2 * (1.0f / (float)PIX);
            out[0] = (m2 > T1_CLIP_F) ? 0.0f : mean;
        }
    }
}

extern "C" void kernel_launch(void* const* d_in, const int* in_sizes, int n_in,
                              void* d_out, int out_size)
{
    // Input order per reference: target, mu, sigma_mu, sigma_n, sigma_y
    const float* target  = (const float*)d_in[0];
    const float* mu      = (const float*)d_in[1];
    const float* sigma_y = (const float*)d_in[4];
    float* out = (float*)d_out;

    maploss_main<<<BLOCKS1, THREADS1>>>(target, mu, sigma_y);
    maploss_finish<<<1, 1024>>>(out);
}